// round 6
// baseline (speedup 1.0000x reference)
#include <cuda_runtime.h>

#define Nn   128
#define Hh   2
#define Ll   1024
#define Cc   (Hh * Ll)      /* 2048 columns = h*L flattened */
#define PRED (Nn * Cc)      /* 262144 */

#define SA2_LD 34           /* u64 lead dim for sA2[m][k]: 128 x 32 (+2 pad) */
#define SB_LD  32           /* f32 lead dim for sB[m][c]: 128 x 32 */

__device__ float g_alpha[PRED];
__device__ float g_Ss[PRED];

// ---- packed fp32x2 helpers (sm_103a FFMA2 path, PTX-only) ------------------
__device__ __forceinline__ unsigned long long pack2(float lo, float hi) {
    unsigned long long r;
    asm("mov.b64 %0, {%1, %2};" : "=l"(r) : "f"(lo), "f"(hi));
    return r;
}
__device__ __forceinline__ void unpack2(unsigned long long v, float& lo, float& hi) {
    asm("mov.b64 {%0, %1}, %2;" : "=f"(lo), "=f"(hi) : "l"(v));
}
__device__ __forceinline__ unsigned long long ffma2(unsigned long long a,
                                                    unsigned long long b,
                                                    unsigned long long c) {
    unsigned long long d;
    asm("fma.rn.f32x2 %0, %1, %2, %3;" : "=l"(d) : "l"(a), "l"(b), "l"(c));
    return d;
}
// direct shared-memory u64 loads (no packing, FFMA2-ready register pairs)
__device__ __forceinline__ void lds_v2u64(unsigned long long& a, unsigned long long& b,
                                          unsigned addr) {
    asm("ld.shared.v2.b64 {%0, %1}, [%2];" : "=l"(a), "=l"(b) : "r"(addr));
}
__device__ __forceinline__ unsigned long long lds_u64(unsigned addr) {
    unsigned long long v;
    asm("ld.shared.b64 %0, [%1];" : "=l"(v) : "r"(addr));
    return v;
}

// ---------------------------------------------------------------------------
// Kernel 1: per-(n,h)-row fused relu + cumsum + exponential-decay recurrence.
// Also emits the third output (Amat + I).
// ---------------------------------------------------------------------------
__global__ void __launch_bounds__(128) scan_kernel(const float* __restrict__ x,
                                                   const float* __restrict__ Amat,
                                                   const float* __restrict__ taus,
                                                   const float* __restrict__ r0dt,
                                                   float* __restrict__ out)
{
    int row  = blockIdx.x;          // n*H + h
    int t    = threadIdx.x;         // 0..127
    int lane = t & 31, wid = t >> 5;
    int base = row * Ll + t * 8;

    const float4* xv = reinterpret_cast<const float4*>(x + base);
    float4 v0 = xv[0], v1 = xv[1];
    float s[8] = { fmaxf(v0.x, 0.f), fmaxf(v0.y, 0.f), fmaxf(v0.z, 0.f), fmaxf(v0.w, 0.f),
                   fmaxf(v1.x, 0.f), fmaxf(v1.y, 0.f), fmaxf(v1.z, 0.f), fmaxf(v1.w, 0.f) };

    // third output: tempAmat.T = Amat + I  (first 128 blocks each do one row)
    if (row < 128) {
        int idx = row * 128 + t;
        out[2 * PRED + idx] = Amat[idx] + (row == t ? 1.f : 0.f);
    }

    float tau = taus[row];
    float R0  = r0dt[row];
    float d   = 1.f - 1.f / tau;

    float cum = 0.f, isv = 0.f;
#pragma unroll
    for (int k = 0; k < 8; k++) { cum += s[k]; isv = fmaf(d, isv, s[k]); }

    float d2 = d * d, d4 = d2 * d2, r8 = d4 * d4;   // d^8

    float inclI = isv, inclC = cum, rp = r8;
#pragma unroll
    for (int off = 1; off < 32; off <<= 1) {
        float ui = __shfl_up_sync(0xffffffffu, inclI, off);
        float uc = __shfl_up_sync(0xffffffffu, inclC, off);
        if (lane >= off) { inclI = fmaf(rp, ui, inclI); inclC += uc; }
        rp *= rp;
    }

    __shared__ float wI[4], wC[4];
    if (lane == 31) { wI[wid] = inclI; wC[wid] = inclC; }
    __syncthreads();

    float Rw = rp;                                  // d^256
    float exI = 0.f, exC = 0.f, aI = 0.f, aC = 0.f;
#pragma unroll
    for (int w = 0; w < 4; w++) {
        if (w == wid) { exI = aI; exC = aC; }
        aI = fmaf(Rw, aI, wI[w]);
        aC += wC[w];
    }

    float upI = __shfl_up_sync(0xffffffffu, inclI, 1);
    float upC = __shfl_up_sync(0xffffffffu, inclC, 1);
    if (lane == 0) { upI = 0.f; upC = 0.f; }
    float XI = fmaf(exI, __powf(r8, (float)lane), upI);
    float XC = upC + exC;

    float al[8], ss[8];
    float ci = XI, cc = XC;
#pragma unroll
    for (int k = 0; k < 8; k++) {
        ci = fmaf(d, ci, s[k]);
        cc += s[k];
        al[k] = 1.f - __expf(-R0 * ci);
        ss[k] = 1.f - cc;
    }

    float4* ga = reinterpret_cast<float4*>(g_alpha + base);
    ga[0] = make_float4(al[0], al[1], al[2], al[3]);
    ga[1] = make_float4(al[4], al[5], al[6], al[7]);
    float4* gs = reinterpret_cast<float4*>(g_Ss + base);
    gs[0] = make_float4(ss[0], ss[1], ss[2], ss[3]);
    gs[1] = make_float4(ss[4], ss[5], ss[6], ss[7]);
    float4* go = reinterpret_cast<float4*>(out + PRED + base);   // signal output
    go[0] = make_float4(s[0], s[1], s[2], s[3]);
    go[1] = make_float4(s[4], s[5], s[6], s[7]);
}

// ---------------------------------------------------------------------------
// Kernel 2: Alpha = alpha + Amat @ alpha ;  pred = Alpha * Ss.
// Grid (64 col-tiles x 4 row-tiles) = 256 blocks; 256 threads; block tile
// 32 rows x 32 cols; thread tile 1 row x 4 cols (2 packed f32x2 accs).
// Mainloop per m: ld.shared.v2.b64 (B) + ld.shared.b64 (A splat) + 2 FFMA2.
// Conflict-free: B warp-read spans 128B; A warp-read spans 32B.
// ---------------------------------------------------------------------------
__global__ void __launch_bounds__(256, 2) gemm_kernel(const float* __restrict__ Amat,
                                                      float* __restrict__ out)
{
    __shared__ unsigned long long sA2[128 * SA2_LD];   // [m][k] splat pairs, 34 KB
    __shared__ float sB[128 * SB_LD];                  // [m][c], 16 KB

    int bx = blockIdx.x;               // 32-col tile (0..63)
    int by = blockIdx.y;               // 32-row tile (0..3)
    int tid = threadIdx.x;
    int k0 = by * 32, c0 = bx * 32;

    // fill sA2[m][k] = (Amat[k0+k][m], Amat[k0+k][m]); coalesced LDG over m
#pragma unroll
    for (int j = 0; j < 16; j++) {
        int i = j * 256 + tid;
        int k = i >> 7, m = i & 127;
        float a = Amat[(k0 + k) * 128 + m];
        sA2[m * SA2_LD + k] = pack2(a, a);
    }
    // fill sB: 1024 float4 quads / 256 threads = 4 iters; conflict-free STS.128
#pragma unroll
    for (int j = 0; j < 4; j++) {
        int i = j * 256 + tid;
        int m = i >> 3, cq = i & 7;
        float4 v = *reinterpret_cast<const float4*>(&g_alpha[m * Cc + c0 + cq * 4]);
        *reinterpret_cast<float4*>(&sB[m * SB_LD + cq * 4]) = v;
    }
    __syncthreads();

    int tx = tid & 7;                  // col quad: local cols 4*tx .. +3
    int ty = tid >> 3;                 // local row 0..31
    int cl = 4 * tx;
    int gk = k0 + ty;

    // hoisted epilogue operand (gmem latency hidden under mainloop)
    const float4 ssv = *reinterpret_cast<const float4*>(&g_Ss[gk * Cc + c0 + cl]);

    unsigned sbB = (unsigned)__cvta_generic_to_shared(sB) + cl * 4;
    unsigned sbA = (unsigned)__cvta_generic_to_shared(sA2) + ty * 8;

    // identity seed: Alpha = alpha + Amat@alpha  (row k0+ty lives in sB)
    unsigned long long acc0, acc1;
    lds_v2u64(acc0, acc1, sbB + (unsigned)(k0 + ty) * (SB_LD * 4));

#pragma unroll 8
    for (int m = 0; m < 128; m++) {
        unsigned long long b0, b1;
        lds_v2u64(b0, b1, sbB + (unsigned)m * (SB_LD * 4));
        unsigned long long ap = lds_u64(sbA + (unsigned)m * (SA2_LD * 8));
        acc0 = ffma2(ap, b0, acc0);
        acc1 = ffma2(ap, b1, acc1);
    }

    float r0, r1, r2, r3;
    unpack2(acc0, r0, r1);
    unpack2(acc1, r2, r3);
    float4 o = make_float4(r0 * ssv.x, r1 * ssv.y, r2 * ssv.z, r3 * ssv.w);
    *reinterpret_cast<float4*>(&out[gk * Cc + c0 + cl]) = o;
}

extern "C" void kernel_launch(void* const* d_in, const int* in_sizes, int n_in,
                              void* d_out, int out_size)
{
    const float* x    = (const float*)d_in[0];
    const float* Amat = (const float*)d_in[1];
    const float* taus = (const float*)d_in[2];
    const float* r0   = (const float*)d_in[3];
    float* out = (float*)d_out;

    (void)in_sizes; (void)n_in; (void)out_size;

    scan_kernel<<<Nn * Hh, 128>>>(x, Amat, taus, r0, out);
    gemm_kernel<<<dim3(64, 4), 256>>>(Amat, out);
}

// round 7
// speedup vs baseline: 1.1604x; 1.1604x over previous
#include <cuda_runtime.h>

#define Nn   128
#define Hh   2
#define Ll   1024
#define Cc   (Hh * Ll)      /* 2048 columns = h*L flattened */
#define PRED (Nn * Cc)      /* 262144 */

#define SA_LD  34           /* u64 lead dim for sA[m][k]: 128 x 32 (+2 pad, keeps 16B align) */
#define SB_LD  64           /* f32 lead dim for sB[m][c]: 128 x 64 */
#define SMEM_A_BYTES (128 * SA_LD * 8)              /* 34816 */
#define SMEM_B_BYTES (128 * SB_LD * 4)              /* 32768 */
#define SMEM_TOTAL   (SMEM_A_BYTES + SMEM_B_BYTES)  /* 67584 */

__device__ float g_alpha[PRED];
__device__ float g_Ss[PRED];

// ---- packed fp32x2 helpers (sm_103a FFMA2 path, PTX-only) ------------------
__device__ __forceinline__ unsigned long long pack2(float lo, float hi) {
    unsigned long long r;
    asm("mov.b64 %0, {%1, %2};" : "=l"(r) : "f"(lo), "f"(hi));
    return r;
}
__device__ __forceinline__ void unpack2(unsigned long long v, float& lo, float& hi) {
    asm("mov.b64 {%0, %1}, %2;" : "=f"(lo), "=f"(hi) : "l"(v));
}
__device__ __forceinline__ unsigned long long ffma2(unsigned long long a,
                                                    unsigned long long b,
                                                    unsigned long long c) {
    unsigned long long d;
    asm("fma.rn.f32x2 %0, %1, %2, %3;" : "=l"(d) : "l"(a), "l"(b), "l"(c));
    return d;
}
__device__ __forceinline__ void lds_v2u64(unsigned long long& a, unsigned long long& b,
                                          unsigned addr) {
    asm("ld.shared.v2.b64 {%0, %1}, [%2];" : "=l"(a), "=l"(b) : "r"(addr));
}
__device__ __forceinline__ void cp_async16(unsigned smem_addr, const void* gptr) {
    asm volatile("cp.async.cg.shared.global [%0], [%1], 16;"
                 :: "r"(smem_addr), "l"(gptr) : "memory");
}

// ---------------------------------------------------------------------------
// Kernel 1: per-(n,h)-row fused relu + cumsum + exponential-decay recurrence.
// Also emits the third output (Amat + I).
// ---------------------------------------------------------------------------
__global__ void __launch_bounds__(128) scan_kernel(const float* __restrict__ x,
                                                   const float* __restrict__ Amat,
                                                   const float* __restrict__ taus,
                                                   const float* __restrict__ r0dt,
                                                   float* __restrict__ out)
{
    int row  = blockIdx.x;          // n*H + h
    int t    = threadIdx.x;         // 0..127
    int lane = t & 31, wid = t >> 5;
    int base = row * Ll + t * 8;

    const float4* xv = reinterpret_cast<const float4*>(x + base);
    float4 v0 = xv[0], v1 = xv[1];
    float s[8] = { fmaxf(v0.x, 0.f), fmaxf(v0.y, 0.f), fmaxf(v0.z, 0.f), fmaxf(v0.w, 0.f),
                   fmaxf(v1.x, 0.f), fmaxf(v1.y, 0.f), fmaxf(v1.z, 0.f), fmaxf(v1.w, 0.f) };

    // third output: tempAmat.T = Amat + I  (first 128 blocks each do one row)
    if (row < 128) {
        int idx = row * 128 + t;
        out[2 * PRED + idx] = Amat[idx] + (row == t ? 1.f : 0.f);
    }

    float tau = taus[row];
    float R0  = r0dt[row];
    float d   = 1.f - 1.f / tau;

    float cum = 0.f, isv = 0.f;
#pragma unroll
    for (int k = 0; k < 8; k++) { cum += s[k]; isv = fmaf(d, isv, s[k]); }

    float d2 = d * d, d4 = d2 * d2, r8 = d4 * d4;   // d^8

    float inclI = isv, inclC = cum, rp = r8;
#pragma unroll
    for (int off = 1; off < 32; off <<= 1) {
        float ui = __shfl_up_sync(0xffffffffu, inclI, off);
        float uc = __shfl_up_sync(0xffffffffu, inclC, off);
        if (lane >= off) { inclI = fmaf(rp, ui, inclI); inclC += uc; }
        rp *= rp;
    }

    __shared__ float wI[4], wC[4];
    if (lane == 31) { wI[wid] = inclI; wC[wid] = inclC; }
    __syncthreads();

    float Rw = rp;                                  // d^256
    float exI = 0.f, exC = 0.f, aI = 0.f, aC = 0.f;
#pragma unroll
    for (int w = 0; w < 4; w++) {
        if (w == wid) { exI = aI; exC = aC; }
        aI = fmaf(Rw, aI, wI[w]);
        aC += wC[w];
    }

    float upI = __shfl_up_sync(0xffffffffu, inclI, 1);
    float upC = __shfl_up_sync(0xffffffffu, inclC, 1);
    if (lane == 0) { upI = 0.f; upC = 0.f; }
    float XI = fmaf(exI, __powf(r8, (float)lane), upI);
    float XC = upC + exC;

    float al[8], ss[8];
    float ci = XI, cc = XC;
#pragma unroll
    for (int k = 0; k < 8; k++) {
        ci = fmaf(d, ci, s[k]);
        cc += s[k];
        al[k] = 1.f - __expf(-R0 * ci);
        ss[k] = 1.f - cc;
    }

    float4* ga = reinterpret_cast<float4*>(g_alpha + base);
    ga[0] = make_float4(al[0], al[1], al[2], al[3]);
    ga[1] = make_float4(al[4], al[5], al[6], al[7]);
    float4* gs = reinterpret_cast<float4*>(g_Ss + base);
    gs[0] = make_float4(ss[0], ss[1], ss[2], ss[3]);
    gs[1] = make_float4(ss[4], ss[5], ss[6], ss[7]);
    float4* go = reinterpret_cast<float4*>(out + PRED + base);   // signal output
    go[0] = make_float4(s[0], s[1], s[2], s[3]);
    go[1] = make_float4(s[4], s[5], s[6], s[7]);
}

// ---------------------------------------------------------------------------
// Kernel 2: Alpha = alpha + Amat @ alpha ;  pred = Alpha * Ss.
// Grid (32 col-tiles x 4 row-tiles) = 128 blocks (ONE wave); 256 threads;
// block tile 32 rows x 64 cols; thread tile 2 rows x 4 cols.
// Mainloop per m: 2x ld.shared.v2.b64 + 4 FFMA2.
// B tile filled with cp.async (no register round-trip).
// ---------------------------------------------------------------------------
__global__ void __launch_bounds__(256) gemm_kernel(const float* __restrict__ Amat,
                                                   float* __restrict__ out)
{
    extern __shared__ unsigned long long smem[];
    unsigned long long* sA = smem;                                   // [m][k] splat pairs
    float* sB = reinterpret_cast<float*>(smem + 128 * SA_LD);        // [m][c]

    int bx = blockIdx.x;               // 64-col tile (0..31)
    int by = blockIdx.y;               // 32-row tile (0..3)
    int tid = threadIdx.x;
    int k0 = by * 32, c0 = bx * 64;

    unsigned sBbase = (unsigned)__cvta_generic_to_shared(sB);
    unsigned sAbase = (unsigned)__cvta_generic_to_shared(sA);

    // B tile via cp.async: 2048 x 16B chunks / 256 threads = 8 each
#pragma unroll
    for (int j = 0; j < 8; j++) {
        int i = j * 256 + tid;
        int m = i >> 4, cq = i & 15;
        cp_async16(sBbase + (unsigned)(m * SB_LD + cq * 4) * 4,
                   &g_alpha[m * Cc + c0 + cq * 4]);
    }
    asm volatile("cp.async.commit_group;" ::: "memory");

    // A tile: splat pairs, coalesced LDG over m (4096 elems / 256 = 16 each)
#pragma unroll
    for (int j = 0; j < 16; j++) {
        int i = j * 256 + tid;
        int k = i >> 7, m = i & 127;
        float a = Amat[(k0 + k) * 128 + m];
        sA[m * SA_LD + k] = pack2(a, a);
    }

    asm volatile("cp.async.wait_group 0;" ::: "memory");
    __syncthreads();

    int tx = tid & 15;                 // col quad: local cols 4*tx .. +3
    int ty = tid >> 4;                 // row pair: local rows 2*ty, 2*ty+1
    int cl = 4 * tx;
    int gk = k0 + 2 * ty;

    // hoisted epilogue operands
    const float4 ssv0 = *reinterpret_cast<const float4*>(&g_Ss[gk * Cc + c0 + cl]);
    const float4 ssv1 = *reinterpret_cast<const float4*>(&g_Ss[(gk + 1) * Cc + c0 + cl]);

    unsigned bB = sBbase + (unsigned)cl * 4;
    unsigned bA = sAbase + (unsigned)ty * 16;

    // identity seed: Alpha = alpha + Amat@alpha  (rows gk, gk+1 live in sB)
    unsigned long long acc00, acc01, acc10, acc11;
    lds_v2u64(acc00, acc01, bB + (unsigned)gk * (SB_LD * 4));
    lds_v2u64(acc10, acc11, bB + (unsigned)(gk + 1) * (SB_LD * 4));

#pragma unroll 16
    for (int m = 0; m < 128; m++) {
        unsigned long long a0, a1, b0, b1;
        lds_v2u64(a0, a1, bA + (unsigned)m * (SA_LD * 8));
        lds_v2u64(b0, b1, bB + (unsigned)m * (SB_LD * 4));
        acc00 = ffma2(a0, b0, acc00);
        acc01 = ffma2(a0, b1, acc01);
        acc10 = ffma2(a1, b0, acc10);
        acc11 = ffma2(a1, b1, acc11);
    }

    float r0, r1, r2, r3;
    unpack2(acc00, r0, r1); unpack2(acc01, r2, r3);
    float4 o0 = make_float4(r0 * ssv0.x, r1 * ssv0.y, r2 * ssv0.z, r3 * ssv0.w);
    *reinterpret_cast<float4*>(&out[gk * Cc + c0 + cl]) = o0;
    unpack2(acc10, r0, r1); unpack2(acc11, r2, r3);
    float4 o1 = make_float4(r0 * ssv1.x, r1 * ssv1.y, r2 * ssv1.z, r3 * ssv1.w);
    *reinterpret_cast<float4*>(&out[(gk + 1) * Cc + c0 + cl]) = o1;
}

extern "C" void kernel_launch(void* const* d_in, const int* in_sizes, int n_in,
                              void* d_out, int out_size)
{
    const float* x    = (const float*)d_in[0];
    const float* Amat = (const float*)d_in[1];
    const float* taus = (const float*)d_in[2];
    const float* r0   = (const float*)d_in[3];
    float* out = (float*)d_out;

    (void)in_sizes; (void)n_in; (void)out_size;

    cudaFuncSetAttribute(gemm_kernel, cudaFuncAttributeMaxDynamicSharedMemorySize,
                         SMEM_TOTAL);

    scan_kernel<<<Nn * Hh, 128>>>(x, Amat, taus, r0, out);
    gemm_kernel<<<dim3(32, 4), 256, SMEM_TOTAL>>>(Amat, out);
}